// round 4
// baseline (speedup 1.0000x reference)
#include <cuda_runtime.h>
#include <cstdint>

// Fixed shapes from reference
#define B_   256
#define T_   2048
#define C_   44                 // A*D floats per (b,t) row
#define C4_  11                 // float4 per row (176 B)
#define SPLIT 4                 // blocks per batch
#define TPB  256
#define T_CHUNK  (T_ / SPLIT)          // 512 t-rows per block
#define F4_CHUNK (T_CHUNK * C4_)       // 5632 float4 per block
#define ITERS    (F4_CHUNK / TPB)      // 22 float4 per thread
#define WIT_ITERS (T_ / TPB)           // 8 witness loads per thread

__device__ __forceinline__ bool is_nan_bits(float f) {
    unsigned u = __float_as_uint(f);
    return (u & 0x7fffffffu) > 0x7f800000u;
}

// One kernel, 4 blocks per batch (grid = 1024 x 256 threads).
// Each block redundantly scans the full witness column [b, :, 0] (the gap
// spans all 44 channels so one element per row is a sufficient witness;
// redundant sectors dedup in L2). The gap boundary is found by EDGE
// DETECTION (valid->NaN gives s, NaN->valid gives e) -- exactly one writer
// each, no atomics, no init. Then the block streams its quarter of the
// batch with unconditional coalesced float4 loads; gap threads interpolate
// from the L2-resident boundary rows.
__global__ void __launch_bounds__(TPB)
fused_interp_kernel(const float* __restrict__ x, float* __restrict__ out) {
    const int blk = blockIdx.x;
    const int b   = blk >> 2;            // batch
    const int q   = blk & (SPLIT - 1);   // quarter within batch
    const int tid = threadIdx.x;

    const float* base = x + (size_t)b * T_ * C_;

    __shared__ float sh_w[T_];           // witness column (8 KB)
    __shared__ int   sh_s, sh_e;

    // ---- Phase 1: witness scan (8 front-batched strided loads/thread) ----
    #pragma unroll
    for (int k = 0; k < WIT_ITERS; k++) {
        const int t = tid + k * TPB;
        sh_w[t] = base[(size_t)t * C_];
    }
    __syncthreads();

    // Edge detect: t=0 and t=T-1 are never NaN by construction
    // (s >= 1, e <= ~1536), so both edges are interior.
    #pragma unroll
    for (int k = 0; k < WIT_ITERS; k++) {
        const int t  = tid + k * TPB;
        const bool n0 = is_nan_bits(sh_w[t]);
        const bool n1 = (t + 1 < T_) ? is_nan_bits(sh_w[t + 1]) : false;
        if (!n0 && n1) sh_s = t;         // last valid before gap
        if (n0 && !n1) sh_e = t + 1;     // first valid after gap
    }
    __syncthreads();

    const int   s   = sh_s;
    const int   e   = sh_e;
    const float inv = 1.0f / (float)(e - s);

    const float4* xs_row = (const float4*)(base + (size_t)s * C_); // L2-hot
    const float4* xe_row = (const float4*)(base + (size_t)e * C_);

    // ---- Phase 2: stream this block's quarter of the batch ----
    const float4* xin  = (const float4*)base;
    float4*       xout = (float4*)(out + (size_t)b * T_ * C_);
    const int lbase = q * F4_CHUNK;

    #pragma unroll 4
    for (int k = 0; k < ITERS; k++) {
        const int idx = lbase + tid + k * TPB;   // float4 index within batch
        const int t   = idx / C4_;
        const int c   = idx - t * C4_;

        float4 v = xin[idx];                     // unconditional, coalesced

        if (t > s && t < e) {
            const float w  = (float)(t - s) * inv;
            const float4 a  = xs_row[c];
            const float4 bb = xe_row[c];
            v.x = fmaf(bb.x - a.x, w, a.x);
            v.y = fmaf(bb.y - a.y, w, a.y);
            v.z = fmaf(bb.z - a.z, w, a.z);
            v.w = fmaf(bb.w - a.w, w, a.w);
        }
        xout[idx] = v;
    }
}

extern "C" void kernel_launch(void* const* d_in, const int* in_sizes, int n_in,
                              void* d_out, int out_size) {
    const float* x = (const float*)d_in[0];
    float* out = (float*)d_out;
    fused_interp_kernel<<<B_ * SPLIT, TPB>>>(x, out);
}

// round 5
// speedup vs baseline: 1.2100x; 1.2100x over previous
#include <cuda_runtime.h>
#include <cstdint>

// Fixed shapes from reference
#define B_    256
#define T_    2048
#define C_    44                 // A*D floats per (b,t) row
#define C4_   11                 // float4 per row (176 B); f4 never crosses a row
#define F4B   (T_ * C4_)         // 22528 float4 per batch
#define SPLIT 8                  // blocks per batch in kernel 1
#define TPB1  256
#define CHUNK (F4B / SPLIT)      // 2816 float4 per block (= 256 t-rows)
#define IT1   (CHUNK / TPB1)     // 11 float4 per thread
#define TPB2  512

// Per-block partial gap bounds {min_t, max_t}; every block rewrites its slot
// on every launch (replay-deterministic, no init pass, no global atomics).
__device__ int2 g_part[B_ * SPLIT];

__device__ __forceinline__ bool is_nan_bits(float f) {
    unsigned u = __float_as_uint(f);
    return (u & 0x7fffffffu) > 0x7f800000u;
}

// Kernel 1: stream-copy the whole tensor; the bulk load doubles as the NaN
// witness (gap rows are NaN in all channels, so v.x classifies the float4).
// NaN float4s skip the store (kernel 2 rewrites the gap) and feed a
// per-block min/max-t reduction.
__global__ void __launch_bounds__(TPB1)
copy_detect_kernel(const float* __restrict__ x, float* __restrict__ out) {
    const int blk = blockIdx.x;
    const int b   = blk / SPLIT;
    const int q   = blk - b * SPLIT;
    const int tid = threadIdx.x;
    const int idx0 = b * F4B + q * CHUNK;

    const float4* __restrict__ xin  = (const float4*)x;
    float4*       __restrict__ xout = (float4*)out;

    __shared__ int s_min, s_max;
    if (tid == 0) { s_min = T_; s_max = -1; }
    __syncthreads();

    int tmin = T_, tmax = -1;

    #pragma unroll
    for (int k = 0; k < IT1; k++) {
        const int idx = idx0 + tid + k * TPB1;
        const float4 v = xin[idx];                 // unconditional, coalesced
        if (!is_nan_bits(v.x)) {
            xout[idx] = v;                         // pass-through
        } else {
            const int t = (idx - b * F4B) / C4_;   // gap row (rare path)
            tmin = min(tmin, t);
            tmax = max(tmax, t);
        }
    }

    if (tmax >= 0) {                               // only gap-touching threads
        atomicMin(&s_min, tmin);
        atomicMax(&s_max, tmax);
    }
    __syncthreads();
    if (tid == 0) g_part[blk] = make_int2(s_min, s_max);
}

// Kernel 2: one block per batch. Reduce the 8 partials -> (s, e), pull the
// two boundary rows (L2-resident: whole input < L2 capacity), write the
// interpolated gap region with coalesced float4 stores.
__global__ void __launch_bounds__(TPB2)
gap_fill_kernel(const float* __restrict__ x, float* __restrict__ out) {
    const int b   = blockIdx.x;
    const int tid = threadIdx.x;

    __shared__ int sh_s, sh_e;
    __shared__ float4 sh_xs[C4_], sh_xe[C4_];

    if (tid == 0) {
        int mn = T_, mx = -1;
        #pragma unroll
        for (int q = 0; q < SPLIT; q++) {
            const int2 p = g_part[b * SPLIT + q];
            mn = min(mn, p.x);
            mx = max(mx, p.y);
        }
        sh_s = mn - 1;                             // last valid before gap
        sh_e = mx + 1;                             // first valid after gap
    }
    __syncthreads();

    const int   s   = sh_s;
    const int   e   = sh_e;
    const float inv = 1.0f / (float)(e - s);

    const float4* base4 = (const float4*)(x + (size_t)b * T_ * C_);
    if (tid < C4_) {
        sh_xs[tid] = base4[(size_t)s * C4_ + tid];
    } else if (tid < 2 * C4_) {
        sh_xe[tid - C4_] = base4[(size_t)e * C4_ + (tid - C4_)];
    }
    __syncthreads();

    float4* xout = (float4*)(out + (size_t)b * T_ * C_);
    const int ngap4 = (e - s - 1) * C4_;           // <= 5632
    const int gbase = (s + 1) * C4_;

    for (int i = tid; i < ngap4; i += TPB2) {
        const int t = (s + 1) + i / C4_;
        const int c = i - (i / C4_) * C4_;
        const float w  = (float)(t - s) * inv;
        const float4 a  = sh_xs[c];
        const float4 bb = sh_xe[c];
        float4 v;
        v.x = fmaf(bb.x - a.x, w, a.x);
        v.y = fmaf(bb.y - a.y, w, a.y);
        v.z = fmaf(bb.z - a.z, w, a.z);
        v.w = fmaf(bb.w - a.w, w, a.w);
        xout[gbase + i] = v;                       // coalesced, contiguous
    }
}

extern "C" void kernel_launch(void* const* d_in, const int* in_sizes, int n_in,
                              void* d_out, int out_size) {
    const float* x = (const float*)d_in[0];
    float* out = (float*)d_out;

    copy_detect_kernel<<<B_ * SPLIT, TPB1>>>(x, out);
    gap_fill_kernel<<<B_, TPB2>>>(x, out);
}

// round 6
// speedup vs baseline: 1.2183x; 1.0068x over previous
#include <cuda_runtime.h>
#include <cstdint>

// Fixed shapes from reference
#define B_    256
#define T_    2048
#define C_    44                 // A*D floats per (b,t) row
#define C4_   11                 // float4 per row (176 B); f4 never crosses a row
#define F4B   (T_ * C4_)         // 22528 float4 per batch
#define SPLIT 8                  // blocks per batch
#define TPB   256
#define CHUNK (F4B / SPLIT)      // 2816 float4 per block (= 256 t-rows)
#define IT1   (CHUNK / TPB)      // 11 float4 per thread

// Per-block partial gap bounds {min_t, max_t} and per-batch arrival counter.
// g_cnt is zero-initialized at module load; the last-arriving block resets it
// to 0 after use, so every graph replay starts clean (replay-deterministic).
__device__ int2 g_part[B_ * SPLIT];
__device__ int  g_cnt[B_];

__device__ __forceinline__ bool is_nan_bits(float f) {
    unsigned u = __float_as_uint(f);
    return (u & 0x7fffffffu) > 0x7f800000u;
}

// Single kernel, 8 blocks per batch (grid = 2048 x 256).
// Phase A (all blocks): stream-copy the chunk; the bulk load doubles as the
//   NaN witness (gap rows are NaN in all channels, so v.x classifies the
//   float4). NaN float4s skip the store and feed a per-block min/max-t
//   reduction, published to g_part.
// Phase B (last arriver per batch only): reduce the 8 partials -> (s, e),
//   interpolate the gap from the two L2-resident boundary rows, write it.
__global__ void __launch_bounds__(TPB)
fused_copy_fill_kernel(const float* __restrict__ x, float* __restrict__ out) {
    const int blk = blockIdx.x;
    const int b   = blk / SPLIT;
    const int q   = blk - b * SPLIT;
    const int tid = threadIdx.x;
    const int idx0 = b * F4B + q * CHUNK;

    const float4* __restrict__ xin  = (const float4*)x;
    float4*       __restrict__ xout = (float4*)out;

    __shared__ int s_min, s_max, s_rank;
    if (tid == 0) { s_min = T_; s_max = -1; }
    __syncthreads();

    // ---- Phase A: copy + detect ----
    int tmin = T_, tmax = -1;
    #pragma unroll
    for (int k = 0; k < IT1; k++) {
        const int idx = idx0 + tid + k * TPB;
        const float4 v = xin[idx];                 // unconditional, coalesced
        if (!is_nan_bits(v.x)) {
            xout[idx] = v;                         // pass-through
        } else {
            const int t = (idx - b * F4B) / C4_;   // gap row (rare path)
            tmin = min(tmin, t);
            tmax = max(tmax, t);
        }
    }
    if (tmax >= 0) {
        atomicMin(&s_min, tmin);
        atomicMax(&s_max, tmax);
    }
    __syncthreads();

    // Publish partial, then arrive on the per-batch counter.
    if (tid == 0) {
        g_part[blk] = make_int2(s_min, s_max);
        __threadfence();                           // order partial before arrive
        s_rank = atomicAdd(&g_cnt[b], 1);
    }
    __syncthreads();
    if (s_rank != SPLIT - 1) return;               // not the last arriver

    // ---- Phase B: last block of this batch fills the gap ----
    __shared__ int sh_s, sh_e;
    if (tid == 0) {
        g_cnt[b] = 0;                              // self-clean for next replay
        __threadfence();                           // acquire: partials visible
        int mn = T_, mx = -1;
        #pragma unroll
        for (int p = 0; p < SPLIT; p++) {
            const int2 pp = g_part[b * SPLIT + p];
            mn = min(mn, pp.x);
            mx = max(mx, pp.y);
        }
        sh_s = mn - 1;                             // last valid before gap
        sh_e = mx + 1;                             // first valid after gap
    }
    __syncthreads();

    const int   s   = sh_s;
    const int   e   = sh_e;
    const float inv = 1.0f / (float)(e - s);

    const float4* base4  = (const float4*)(x + (size_t)b * T_ * C_);
    const float4* xs_row = base4 + (size_t)s * C4_;   // L2-hot (just streamed)
    const float4* xe_row = base4 + (size_t)e * C4_;
    float4* bout = (float4*)(out + (size_t)b * T_ * C_);

    const int ngap4 = (e - s - 1) * C4_;           // <= 5632
    const int gbase = (s + 1) * C4_;

    for (int i = tid; i < ngap4; i += TPB) {
        const int dt = i / C4_;
        const int c  = i - dt * C4_;
        const float w  = (float)(dt + 1) * inv;
        const float4 a  = xs_row[c];
        const float4 bb = xe_row[c];
        float4 v;
        v.x = fmaf(bb.x - a.x, w, a.x);
        v.y = fmaf(bb.y - a.y, w, a.y);
        v.z = fmaf(bb.z - a.z, w, a.z);
        v.w = fmaf(bb.w - a.w, w, a.w);
        bout[gbase + i] = v;                       // coalesced, contiguous
    }
}

extern "C" void kernel_launch(void* const* d_in, const int* in_sizes, int n_in,
                              void* d_out, int out_size) {
    const float* x = (const float*)d_in[0];
    float* out = (float*)d_out;
    fused_copy_fill_kernel<<<B_ * SPLIT, TPB>>>(x, out);
}